// round 12
// baseline (speedup 1.0000x reference)
#include <cuda_runtime.h>
#include <math.h>

#define T_STEPS 16384
#define IDIM 1024
#define HDIM 1024
#define GDIM 4096
#define NBLK 128
#define RTHREADS 256
#define NSHARD 32                        // counter shards, one 128B line each
#define CTAS_PER_SHARD (NBLK / NSHARD)   // 4

// ---------------- device globals (scratch; no allocations allowed) ------------
__device__ float g_xgates[(size_t)T_STEPS * GDIM];   // 256 MB input gates
__device__ __align__(16) float g_h[2][HDIM];         // double-buffered hidden state
__device__ unsigned g_ctr[NSHARD * 32];              // 32 counters, 128B apart

// ---------------- helpers -----------------------------------------------------
static __device__ __forceinline__ unsigned long long pk2(float lo, float hi) {
    unsigned long long r;
    asm("mov.b64 %0, {%1, %2};" : "=l"(r) : "f"(lo), "f"(hi));
    return r;
}
static __device__ __forceinline__ void fma2(unsigned long long& d,
                                            unsigned long long a,
                                            unsigned long long b) {
    asm("fma.rn.f32x2 %0, %1, %2, %0;" : "+l"(d) : "l"(a), "l"(b));
}
static __device__ __forceinline__ float2 up2(unsigned long long v) {
    float2 f;
    asm("mov.b64 {%0, %1}, %2;" : "=f"(f.x), "=f"(f.y) : "l"(v));
    return f;
}
static __device__ __forceinline__ float fast_sigmoid(float x) {
    return __fdividef(1.0f, 1.0f + __expf(-x));
}
static __device__ __forceinline__ float fast_tanh(float x) {
    return 1.0f - __fdividef(2.0f, __expf(2.0f * x) + 1.0f);
}
static __device__ __forceinline__ unsigned ld_acq(const unsigned* p) {
    unsigned v;
    asm volatile("ld.acquire.gpu.u32 %0, [%1];" : "=r"(v) : "l"(p) : "memory");
    return v;
}
static __device__ __forceinline__ void red_rel(unsigned* p) {
    asm volatile("red.release.gpu.add.u32 [%0], %1;" :: "l"(p), "r"(1u) : "memory");
}
// Shared-memory acq_rel arrival counter (R11-proven): release orders the
// warp's prior global h store before the arrival; the 8th arriver's acquire
// pulls all earlier warps' stores into its happens-before set before it
// issues the gpu-scope release.
static __device__ __forceinline__ unsigned atom_arrive_sh(unsigned* p) {
    unsigned old;
    unsigned addr = (unsigned)__cvta_generic_to_shared(p);
    asm volatile("atom.acq_rel.cta.shared::cta.add.u32 %0, [%1], %2;"
                 : "=r"(old) : "r"(addr), "r"(1u) : "memory");
    return old;
}

// ---------------- init: reset counters each launch (graph replays!) -----------
__global__ void init_kernel() {
    int i = threadIdx.x + blockIdx.x * blockDim.x;
    if (i < NSHARD * 32) g_ctr[i] = 0u;
}

// ---------------- GEMM: x_gates = A @ W_ih^T + (b_ih + b_hh) ------------------
// (unchanged; proven R1/R5)
__global__ __launch_bounds__(256) void gemm_kernel(
    const float* __restrict__ A, const float* __restrict__ W,
    const float* __restrict__ bih, const float* __restrict__ bhh) {
    __shared__ float As[8][132];
    __shared__ float Bs[8][132];

    const int tid = threadIdx.x;
    const int m0 = blockIdx.x * 128;
    const int n0 = blockIdx.y * 128;
    const int lrow = tid >> 1;
    const int kq = (tid & 1) * 4;
    const int tm = (tid & 15) * 8;
    const int tn = (tid >> 4) * 8;

    unsigned long long acc[4][8];
#pragma unroll
    for (int i = 0; i < 4; i++)
#pragma unroll
        for (int j = 0; j < 8; j++) acc[i][j] = 0ULL;

    const float* aptr = A + (size_t)(m0 + lrow) * IDIM + kq;
    const float* wptr = W + (size_t)(n0 + lrow) * IDIM + kq;

    float4 av = *(const float4*)aptr;
    float4 bv = *(const float4*)wptr;

    for (int k0 = 0; k0 < IDIM; k0 += 8) {
        __syncthreads();
        As[kq + 0][lrow] = av.x; As[kq + 1][lrow] = av.y;
        As[kq + 2][lrow] = av.z; As[kq + 3][lrow] = av.w;
        Bs[kq + 0][lrow] = bv.x; Bs[kq + 1][lrow] = bv.y;
        Bs[kq + 2][lrow] = bv.z; Bs[kq + 3][lrow] = bv.w;
        __syncthreads();
        if (k0 + 8 < IDIM) {
            av = *(const float4*)(aptr + k0 + 8);
            bv = *(const float4*)(wptr + k0 + 8);
        }
#pragma unroll
        for (int k = 0; k < 8; k++) {
            float4 a0 = *(const float4*)&As[k][tm];
            float4 a1 = *(const float4*)&As[k][tm + 4];
            float4 b0 = *(const float4*)&Bs[k][tn];
            float4 b1 = *(const float4*)&Bs[k][tn + 4];
            unsigned long long am[4] = { pk2(a0.x, a0.y), pk2(a0.z, a0.w),
                                         pk2(a1.x, a1.y), pk2(a1.z, a1.w) };
            float bb[8] = { b0.x, b0.y, b0.z, b0.w, b1.x, b1.y, b1.z, b1.w };
#pragma unroll
            for (int j = 0; j < 8; j++) {
                unsigned long long b2 = pk2(bb[j], bb[j]);
                fma2(acc[0][j], am[0], b2);
                fma2(acc[1][j], am[1], b2);
                fma2(acc[2][j], am[2], b2);
                fma2(acc[3][j], am[3], b2);
            }
        }
    }

    float bias[8];
#pragma unroll
    for (int j = 0; j < 8; j++) bias[j] = bih[n0 + tn + j] + bhh[n0 + tn + j];

#pragma unroll
    for (int i = 0; i < 4; i++) {
        float r0v[8], r1v[8];
#pragma unroll
        for (int j = 0; j < 8; j++) {
            float2 p = up2(acc[i][j]);
            r0v[j] = p.x + bias[j];
            r1v[j] = p.y + bias[j];
        }
        size_t row0 = (size_t)(m0 + tm + 2 * i) * GDIM + n0 + tn;
        size_t row1 = row0 + GDIM;
        *(float4*)&g_xgates[row0]     = make_float4(r0v[0], r0v[1], r0v[2], r0v[3]);
        *(float4*)&g_xgates[row0 + 4] = make_float4(r0v[4], r0v[5], r0v[6], r0v[7]);
        *(float4*)&g_xgates[row1]     = make_float4(r1v[0], r1v[1], r1v[2], r1v[3]);
        *(float4*)&g_xgates[row1 + 4] = make_float4(r1v[4], r1v[5], r1v[6], r1v[7]);
    }
}

// ---------------- persistent LSTM recurrence ----------------------------------
// R5 protocol with two structural cuts driven by the L2-atomic law:
//   * 32 counter shards (4 CTAs each): arrival queue 437 -> ~108 cyc.
//     Poll: warp 0, lane l watches shard l (one ballot round over 32 lines),
//     then ONE __syncthreads broadcasts the trigger.
//   * h loaded DIRECTLY to registers (lane l -> h[l+32j], matching the weight
//     map): smem staging, its fill stores, LDS latency and the second barrier
//     all disappear. (4 MB/step of L2 reads ~ 160 cyc chip-wide, overlapped.)
// Publication: lane0 st.cg + smem acq_rel arrival; 8th warp fires ONE
// red.release per CTA (R11-proven ordering chain).
// Overwrite safety: unchanged R5 argument — poll t+1 passes only after every
// warp everywhere arrived for t+1, and each arrival is data-ordered after that
// warp's h(t) loads were consumed into registers.
__global__ __launch_bounds__(RTHREADS, 1) void lstm_kernel(const float* __restrict__ Whh) {
    __shared__ unsigned sh_arrive;      // monotone arrival counter (8 per step)

    const int tid = threadIdx.x;
    const int w = tid >> 5;             // warp 0..7
    const int lane = tid & 31;
    const int b = blockIdx.x;           // 0..127
    const int e = b * 8 + w;            // owned h element
    const int shard = b >> 2;           // 4 CTAs per shard

    unsigned long long w01[32], w23[32];
#pragma unroll
    for (int c0 = 0; c0 < 32; c0++) {
        int col = lane + 32 * c0;
        w01[c0] = pk2(Whh[(size_t)(0 * HDIM + e) * HDIM + col],
                      Whh[(size_t)(1 * HDIM + e) * HDIM + col]);
        w23[c0] = pk2(Whh[(size_t)(2 * HDIM + e) * HDIM + col],
                      Whh[(size_t)(3 * HDIM + e) * HDIM + col]);
    }

    if (tid == 0) sh_arrive = 0u;
    __syncthreads();

    float c_state = 0.0f;               // lane 0's value is authoritative

    // xg for step 0 (lanes 0..3: one gate each); prefetched a step ahead.
    float xg_cur = 0.0f, xg_next = 0.0f;
    if (lane < 4) xg_cur = __ldcg(&g_xgates[(size_t)0 * GDIM + lane * HDIM + e]);

    for (int t = 0; t < T_STEPS; t++) {
        // Issue next step's xg load before any stalling (a full step to land).
        if (lane < 4 && t + 1 < T_STEPS)
            xg_next = __ldcg(&g_xgates[(size_t)(t + 1) * GDIM + lane * HDIM + e]);

        float hreg[32];
        if (t > 0) {
            if (w == 0) {               // warp 0: lane l polls shard l
                const unsigned target = (unsigned)t * CTAS_PER_SHARD;
                int probes = 0;
                for (;;) {
                    unsigned v = ld_acq(&g_ctr[lane * 32]);
                    if (__all_sync(0xffffffffu, v >= target)) break;
                    if (++probes > 1024) __nanosleep(64);
                }
            }
            __syncthreads();            // broadcast trigger + acquired visibility
            const float* hb = g_h[t & 1];
#pragma unroll
            for (int j = 0; j < 32; j++)
                hreg[j] = __ldcg(hb + lane + 32 * j);   // coalesced, reg-direct
        } else {
#pragma unroll
            for (int j = 0; j < 32; j++) hreg[j] = 0.0f;
        }

        unsigned long long acc01 = 0ULL, acc23 = 0ULL;
#pragma unroll
        for (int j = 0; j < 32; j++) {
            unsigned long long hh = pk2(hreg[j], hreg[j]);
            fma2(acc01, w01[j], hh);
            fma2(acc23, w23[j], hh);
        }

        float2 s01 = up2(acc01), s23 = up2(acc23);
#pragma unroll
        for (int off = 16; off; off >>= 1) {
            s01.x += __shfl_xor_sync(0xffffffffu, s01.x, off);
            s01.y += __shfl_xor_sync(0xffffffffu, s01.y, off);
            s23.x += __shfl_xor_sync(0xffffffffu, s23.x, off);
            s23.y += __shfl_xor_sync(0xffffffffu, s23.y, off);
        }

        // Parallel activations: lane k (0..3) computes its gate.
        float pre = (lane == 0) ? s01.x : (lane == 1) ? s01.y
                  : (lane == 2) ? s23.x : s23.y;
        float a = pre + xg_cur;                      // xg_cur valid lanes 0..3
        float act = (lane == 2) ? fast_tanh(a) : fast_sigmoid(a);
        float f_ = __shfl_sync(0xffffffffu, act, 1);
        float g_ = __shfl_sync(0xffffffffu, act, 2);
        float o_ = __shfl_sync(0xffffffffu, act, 3);

        if (lane == 0) {
            c_state = f_ * c_state + act * g_;       // act = i on lane 0
            float hn = o_ * fast_tanh(c_state);
            __stcg(&g_h[(t + 1) & 1][e], hn);        // publish h(t+1)[e]
            unsigned old = atom_arrive_sh(&sh_arrive);
            if (old == 8u * (unsigned)t + 7u)        // 8th warp of this step
                red_rel(&g_ctr[shard * 32]);         // ONE arrival per CTA
        }

        xg_cur = xg_next;
    }
}

// ---------------- final: out = W_lin @ h_last + b_lin -------------------------
__global__ void final_kernel(const float* __restrict__ Wl,
                             const float* __restrict__ bl,
                             float* __restrict__ out) {
    __shared__ float partial[32];
    const int tid = threadIdx.x;     // 1024 threads
    float v = Wl[tid] * g_h[0][tid]; // h(T) lives in buffer (T_STEPS & 1) == 0
#pragma unroll
    for (int off = 16; off; off >>= 1) v += __shfl_xor_sync(0xffffffffu, v, off);
    if ((tid & 31) == 0) partial[tid >> 5] = v;
    __syncthreads();
    if (tid < 32) {
        float s = partial[tid];
#pragma unroll
        for (int off = 16; off; off >>= 1) s += __shfl_xor_sync(0xffffffffu, s, off);
        if (tid == 0) out[0] = s + bl[0];
    }
}

// ---------------- launch -------------------------------------------------------
extern "C" void kernel_launch(void* const* d_in, const int* in_sizes, int n_in,
                              void* d_out, int out_size) {
    const float* input = (const float*)d_in[0];   // [T, I]
    const float* W_ih  = (const float*)d_in[1];   // [4H, I]
    const float* W_hh  = (const float*)d_in[2];   // [4H, H]
    const float* b_ih  = (const float*)d_in[3];   // [4H]
    const float* b_hh  = (const float*)d_in[4];   // [4H]
    const float* W_lin = (const float*)d_in[5];   // [1, H]
    const float* b_lin = (const float*)d_in[6];   // [1]
    float* out = (float*)d_out;

    init_kernel<<<4, 256>>>();

    dim3 ggrid(T_STEPS / 128, GDIM / 128);        // (128, 32)
    gemm_kernel<<<ggrid, 256>>>(input, W_ih, b_ih, b_hh);

    lstm_kernel<<<NBLK, RTHREADS>>>(W_hh);

    final_kernel<<<1, 1024>>>(W_lin, b_lin, out);
}

// round 13
// speedup vs baseline: 1.2917x; 1.2917x over previous
#include <cuda_runtime.h>
#include <math.h>

#define T_STEPS 16384
#define IDIM 1024
#define HDIM 1024
#define NBLK 128
#define RTHREADS 256
#define NGRP 8                          // counter shards, one 128B line each
#define CTAS_PER_GRP (NBLK / NGRP)      // 16

// Dynamic smem layout (per CTA):
//   [0)        u64 Wp01[8][1024]  64 KB  {W_ih[g0][c], W_ih[g1][c]} per warp
//   [65536)    u64 Wp23[8][1024]  64 KB  {W_ih[g2][c], W_ih[g3][c]}
//   [131072)   float ibuf[1024]    4 KB  staged input row
//   [135168)   float sh_h[1024]    4 KB  staged hidden state
#define SMEM_BYTES (131072 + 4096 + 4096)

// ---------------- device globals (scratch; no allocations allowed) ------------
__device__ __align__(16) float g_h[2][HDIM];         // double-buffered hidden state
__device__ unsigned g_ctr[NGRP * 32];                // 8 counters, 128B apart

// ---------------- helpers -----------------------------------------------------
static __device__ __forceinline__ unsigned long long pk2(float lo, float hi) {
    unsigned long long r;
    asm("mov.b64 %0, {%1, %2};" : "=l"(r) : "f"(lo), "f"(hi));
    return r;
}
static __device__ __forceinline__ void fma2(unsigned long long& d,
                                            unsigned long long a,
                                            unsigned long long b) {
    asm("fma.rn.f32x2 %0, %1, %2, %0;" : "+l"(d) : "l"(a), "l"(b));
}
static __device__ __forceinline__ float2 up2(unsigned long long v) {
    float2 f;
    asm("mov.b64 {%0, %1}, %2;" : "=f"(f.x), "=f"(f.y) : "l"(v));
    return f;
}
static __device__ __forceinline__ float fast_sigmoid(float x) {
    return __fdividef(1.0f, 1.0f + __expf(-x));
}
static __device__ __forceinline__ float fast_tanh(float x) {
    return 1.0f - __fdividef(2.0f, __expf(2.0f * x) + 1.0f);
}
static __device__ __forceinline__ unsigned ld_acq(const unsigned* p) {
    unsigned v;
    asm volatile("ld.acquire.gpu.u32 %0, [%1];" : "=r"(v) : "l"(p) : "memory");
    return v;
}
static __device__ __forceinline__ void red_rel(unsigned* p) {
    asm volatile("red.release.gpu.add.u32 [%0], %1;" :: "l"(p), "r"(1u) : "memory");
}

// ---------------- init: reset counters each launch (graph replays!) -----------
__global__ void init_kernel() {
    int i = threadIdx.x;
    if (i < NGRP * 32) g_ctr[i] = 0u;
}

// ---------------- fused persistent LSTM (recurrence + on-the-fly x-gates) -----
// Recurrence protocol: BYTE-EXACT R5 (best: 34.4 ms). 128 CTAs x 8 warps;
// warp w of CTA b owns h element e = b*8 + w; W_hh in registers; smem h
// staging; 8 acquire-polled counter shards; one red.release per CTA per step.
// NEW: the input GEMM is fused into the idle window. Each CTA holds its 32
// W_ih rows in smem (g-paired u64). Per step t: the existing fill phase also
// stages input row t+1 into ibuf (same barriers cover it); AFTER the CTA's
// red.release (off the inter-CTA critical path) each warp dots ibuf against
// its 4 W_ih rows -> xg[t+1] in lane-0 registers. The separate GEMM kernel,
// the 256 MB x_gates buffer and its DRAM traffic are gone.
// ibuf race-freedom: step-(t+1) fill overwrites ibuf only after the post-poll
// __syncthreads, which every warp reaches only after finishing its step-t dot.
__global__ __launch_bounds__(RTHREADS, 1) void lstm_kernel(
    const float* __restrict__ Whh, const float* __restrict__ Wih,
    const float* __restrict__ input,
    const float* __restrict__ bih, const float* __restrict__ bhh) {
    extern __shared__ char smem[];
    unsigned long long* Wp01 = (unsigned long long*)smem;            // [8][1024]
    unsigned long long* Wp23 = (unsigned long long*)(smem + 65536);  // [8][1024]
    float* ibuf = (float*)(smem + 131072);                           // [1024]
    float* sh_h = (float*)(smem + 135168);                           // [1024]

    const int tid = threadIdx.x;
    const int w = tid >> 5;             // warp 0..7
    const int lane = tid & 31;
    const int b = blockIdx.x;           // 0..127
    const int e = b * 8 + w;            // owned h element
    const int grp = b >> 4;             // counter shard

    // W_hh slice -> registers (R5 layout).
    unsigned long long w01[32], w23[32];
#pragma unroll
    for (int c0 = 0; c0 < 32; c0++) {
        int col = lane + 32 * c0;
        w01[c0] = pk2(Whh[(size_t)(0 * HDIM + e) * HDIM + col],
                      Whh[(size_t)(1 * HDIM + e) * HDIM + col]);
        w23[c0] = pk2(Whh[(size_t)(2 * HDIM + e) * HDIM + col],
                      Whh[(size_t)(3 * HDIM + e) * HDIM + col]);
    }

    // W_ih slice -> smem, g-paired: Wp01[w][c] = {W[0H+e][c], W[1H+e][c]}.
    for (int idx = tid; idx < 8 * IDIM; idx += RTHREADS) {
        int wi = idx >> 10;             // warp slot 0..7
        int col = idx & 1023;
        int ee = b * 8 + wi;
        Wp01[idx] = pk2(Wih[(size_t)(0 * HDIM + ee) * IDIM + col],
                        Wih[(size_t)(1 * HDIM + ee) * IDIM + col]);
        Wp23[idx] = pk2(Wih[(size_t)(2 * HDIM + ee) * IDIM + col],
                        Wih[(size_t)(3 * HDIM + ee) * IDIM + col]);
    }
    // Bias (for lane 0's epilogue): b_ih + b_hh per gate.
    const float bias0 = bih[0 * HDIM + e] + bhh[0 * HDIM + e];
    const float bias1 = bih[1 * HDIM + e] + bhh[1 * HDIM + e];
    const float bias2 = bih[2 * HDIM + e] + bhh[2 * HDIM + e];
    const float bias3 = bih[3 * HDIM + e] + bhh[3 * HDIM + e];

    // Stage input row 0 and compute xg[0].
    ((float4*)ibuf)[tid] = __ldcg(&((const float4*)input)[tid]);  // row 0
    __syncthreads();

    float xg0, xg1, xg2, xg3;
    {
        unsigned long long a01 = 0ULL, a23 = 0ULL;
#pragma unroll 8
        for (int j = 0; j < 32; j++) {
            int c = lane + 32 * j;
            float iv = ibuf[c];
            unsigned long long hh = pk2(iv, iv);
            fma2(a01, Wp01[w * IDIM + c], hh);
            fma2(a23, Wp23[w * IDIM + c], hh);
        }
        float2 s01 = up2(a01), s23 = up2(a23);
#pragma unroll
        for (int off = 16; off; off >>= 1) {
            s01.x += __shfl_xor_sync(0xffffffffu, s01.x, off);
            s01.y += __shfl_xor_sync(0xffffffffu, s01.y, off);
            s23.x += __shfl_xor_sync(0xffffffffu, s23.x, off);
            s23.y += __shfl_xor_sync(0xffffffffu, s23.y, off);
        }
        xg0 = s01.x + bias0; xg1 = s01.y + bias1;
        xg2 = s23.x + bias2; xg3 = s23.y + bias3;
    }
    __syncthreads();   // xg[0] dots done before loop's ibuf overwrite

    float c_state = 0.0f;               // lane 0's value is authoritative

    for (int t = 0; t < T_STEPS; t++) {
        // ---- wait + stage (EXACT R5 protocol) ----
        if (t > 0) {
            if (tid < NGRP) {
                const unsigned target = (unsigned)t * CTAS_PER_GRP;
                unsigned v;
                do {
                    v = ld_acq(&g_ctr[tid * 32]);
                } while (v < target);
            }
            __syncthreads();            // post-poll: acquired visibility + gates ibuf
            const float4* hb = (const float4*)g_h[t & 1];
            ((float4*)sh_h)[tid] = __ldcg(&hb[tid]);
        } else {
            ((float4*)sh_h)[tid] = make_float4(0.f, 0.f, 0.f, 0.f);
        }
        // Stage next input row alongside h (covered by same barrier pair).
        if (t + 1 < T_STEPS)
            ((float4*)ibuf)[tid] =
                __ldcg(&((const float4*)(input + (size_t)(t + 1) * IDIM))[tid]);
        __syncthreads();                // post-fill

        // ---- recurrent GEMV (R5) ----
        unsigned long long acc01 = 0ULL, acc23 = 0ULL;
#pragma unroll
        for (int c0 = 0; c0 < 32; c0++) {
            float hv = sh_h[lane + 32 * c0];        // bank = lane: conflict-free
            unsigned long long hh = pk2(hv, hv);
            fma2(acc01, w01[c0], hh);
            fma2(acc23, w23[c0], hh);
        }
        __syncthreads();   // sh_h consumed; safe to refill next iteration

        float2 s01 = up2(acc01), s23 = up2(acc23);
#pragma unroll
        for (int off = 16; off; off >>= 1) {
            s01.x += __shfl_xor_sync(0xffffffffu, s01.x, off);
            s01.y += __shfl_xor_sync(0xffffffffu, s01.y, off);
            s23.x += __shfl_xor_sync(0xffffffffu, s23.x, off);
            s23.y += __shfl_xor_sync(0xffffffffu, s23.y, off);
        }

        if (lane == 0) {
            float i_ = fast_sigmoid(s01.x + xg0);
            float f_ = fast_sigmoid(s01.y + xg1);
            float g_ = fast_tanh(s23.x + xg2);
            float o_ = fast_sigmoid(s23.y + xg3);
            c_state = f_ * c_state + i_ * g_;
            float hn = o_ * fast_tanh(c_state);
            __stcg(&g_h[(t + 1) & 1][e], hn);
        }
        __syncthreads();   // all 8 h-stores of this CTA issued before arrival

        if (tid == 0) red_rel(&g_ctr[grp * 32]);   // publish step completion

        // ---- fused x-gate dot for step t+1 (OFF the inter-CTA critical path:
        //      runs after our release; other CTAs already see our arrival) ----
        if (t + 1 < T_STEPS) {
            unsigned long long a01 = 0ULL, a23 = 0ULL;
#pragma unroll 8
            for (int j = 0; j < 32; j++) {
                int c = lane + 32 * j;
                float iv = ibuf[c];
                unsigned long long hh = pk2(iv, iv);
                fma2(a01, Wp01[w * IDIM + c], hh);
                fma2(a23, Wp23[w * IDIM + c], hh);
            }
            float2 t01 = up2(a01), t23 = up2(a23);
#pragma unroll
            for (int off = 16; off; off >>= 1) {
                t01.x += __shfl_xor_sync(0xffffffffu, t01.x, off);
                t01.y += __shfl_xor_sync(0xffffffffu, t01.y, off);
                t23.x += __shfl_xor_sync(0xffffffffu, t23.x, off);
                t23.y += __shfl_xor_sync(0xffffffffu, t23.y, off);
            }
            xg0 = t01.x + bias0; xg1 = t01.y + bias1;
            xg2 = t23.x + bias2; xg3 = t23.y + bias3;
        }
    }
}

// ---------------- final: out = W_lin @ h_last + b_lin -------------------------
__global__ void final_kernel(const float* __restrict__ Wl,
                             const float* __restrict__ bl,
                             float* __restrict__ out) {
    __shared__ float partial[32];
    const int tid = threadIdx.x;     // 1024 threads
    float v = Wl[tid] * g_h[0][tid]; // h(T) lives in buffer (T_STEPS & 1) == 0
#pragma unroll
    for (int off = 16; off; off >>= 1) v += __shfl_xor_sync(0xffffffffu, v, off);
    if ((tid & 31) == 0) partial[tid >> 5] = v;
    __syncthreads();
    if (tid < 32) {
        float s = partial[tid];
#pragma unroll
        for (int off = 16; off; off >>= 1) s += __shfl_xor_sync(0xffffffffu, s, off);
        if (tid == 0) out[0] = s + bl[0];
    }
}

// ---------------- launch -------------------------------------------------------
extern "C" void kernel_launch(void* const* d_in, const int* in_sizes, int n_in,
                              void* d_out, int out_size) {
    const float* input = (const float*)d_in[0];   // [T, I]
    const float* W_ih  = (const float*)d_in[1];   // [4H, I]
    const float* W_hh  = (const float*)d_in[2];   // [4H, H]
    const float* b_ih  = (const float*)d_in[3];   // [4H]
    const float* b_hh  = (const float*)d_in[4];   // [4H]
    const float* W_lin = (const float*)d_in[5];   // [1, H]
    const float* b_lin = (const float*)d_in[6];   // [1]
    float* out = (float*)d_out;

    // Opt in to >48KB dynamic smem (idempotent; not a stream op, capture-safe).
    cudaFuncSetAttribute(lstm_kernel,
                         cudaFuncAttributeMaxDynamicSharedMemorySize, SMEM_BYTES);

    init_kernel<<<1, 256>>>();
    lstm_kernel<<<NBLK, RTHREADS, SMEM_BYTES>>>(W_hh, W_ih, input, b_ih, b_hh);
    final_kernel<<<1, 1024>>>(W_lin, b_lin, out);
}

// round 14
// speedup vs baseline: 1.5028x; 1.1635x over previous
#include <cuda_runtime.h>
#include <math.h>

#define T_STEPS 16384
#define IDIM 1024
#define HDIM 1024
#define GDIM 4096
#define NBLK 128
#define RTHREADS 256
#define NSHARD 32                        // counter shards, one 128B line each
#define CTAS_PER_SHARD (NBLK / NSHARD)   // 4  -> arrival queue ~110 cyc (vs 437)

// ---------------- device globals (scratch; no allocations allowed) ------------
__device__ float g_xgates[(size_t)T_STEPS * GDIM];   // 256 MB input gates
__device__ __align__(16) float g_h[2][HDIM];         // double-buffered hidden state
__device__ unsigned g_ctr[NSHARD * 32];              // 32 counters, 128B apart

// ---------------- helpers -----------------------------------------------------
static __device__ __forceinline__ unsigned long long pk2(float lo, float hi) {
    unsigned long long r;
    asm("mov.b64 %0, {%1, %2};" : "=l"(r) : "f"(lo), "f"(hi));
    return r;
}
static __device__ __forceinline__ void fma2(unsigned long long& d,
                                            unsigned long long a,
                                            unsigned long long b) {
    asm("fma.rn.f32x2 %0, %1, %2, %0;" : "+l"(d) : "l"(a), "l"(b));
}
static __device__ __forceinline__ float2 up2(unsigned long long v) {
    float2 f;
    asm("mov.b64 {%0, %1}, %2;" : "=f"(f.x), "=f"(f.y) : "l"(v));
    return f;
}
static __device__ __forceinline__ float fast_sigmoid(float x) {
    return __fdividef(1.0f, 1.0f + __expf(-x));
}
static __device__ __forceinline__ float fast_tanh(float x) {
    return 1.0f - __fdividef(2.0f, __expf(2.0f * x) + 1.0f);
}
static __device__ __forceinline__ unsigned ld_acq(const unsigned* p) {
    unsigned v;
    asm volatile("ld.acquire.gpu.u32 %0, [%1];" : "=r"(v) : "l"(p) : "memory");
    return v;
}
static __device__ __forceinline__ void red_rel(unsigned* p) {
    asm volatile("red.release.gpu.add.u32 [%0], %1;" :: "l"(p), "r"(1u) : "memory");
}

// ---------------- init: reset counters each launch (graph replays!) -----------
__global__ void init_kernel() {
    int i = threadIdx.x + blockIdx.x * blockDim.x;
    if (i < NSHARD * 32) g_ctr[i] = 0u;
}

// ---------------- GEMM: x_gates = A @ W_ih^T + (b_ih + b_hh) ------------------
// (unchanged; proven R1/R5)
__global__ __launch_bounds__(256) void gemm_kernel(
    const float* __restrict__ A, const float* __restrict__ W,
    const float* __restrict__ bih, const float* __restrict__ bhh) {
    __shared__ float As[8][132];
    __shared__ float Bs[8][132];

    const int tid = threadIdx.x;
    const int m0 = blockIdx.x * 128;
    const int n0 = blockIdx.y * 128;
    const int lrow = tid >> 1;
    const int kq = (tid & 1) * 4;
    const int tm = (tid & 15) * 8;
    const int tn = (tid >> 4) * 8;

    unsigned long long acc[4][8];
#pragma unroll
    for (int i = 0; i < 4; i++)
#pragma unroll
        for (int j = 0; j < 8; j++) acc[i][j] = 0ULL;

    const float* aptr = A + (size_t)(m0 + lrow) * IDIM + kq;
    const float* wptr = W + (size_t)(n0 + lrow) * IDIM + kq;

    float4 av = *(const float4*)aptr;
    float4 bv = *(const float4*)wptr;

    for (int k0 = 0; k0 < IDIM; k0 += 8) {
        __syncthreads();
        As[kq + 0][lrow] = av.x; As[kq + 1][lrow] = av.y;
        As[kq + 2][lrow] = av.z; As[kq + 3][lrow] = av.w;
        Bs[kq + 0][lrow] = bv.x; Bs[kq + 1][lrow] = bv.y;
        Bs[kq + 2][lrow] = bv.z; Bs[kq + 3][lrow] = bv.w;
        __syncthreads();
        if (k0 + 8 < IDIM) {
            av = *(const float4*)(aptr + k0 + 8);
            bv = *(const float4*)(wptr + k0 + 8);
        }
#pragma unroll
        for (int k = 0; k < 8; k++) {
            float4 a0 = *(const float4*)&As[k][tm];
            float4 a1 = *(const float4*)&As[k][tm + 4];
            float4 b0 = *(const float4*)&Bs[k][tn];
            float4 b1 = *(const float4*)&Bs[k][tn + 4];
            unsigned long long am[4] = { pk2(a0.x, a0.y), pk2(a0.z, a0.w),
                                         pk2(a1.x, a1.y), pk2(a1.z, a1.w) };
            float bb[8] = { b0.x, b0.y, b0.z, b0.w, b1.x, b1.y, b1.z, b1.w };
#pragma unroll
            for (int j = 0; j < 8; j++) {
                unsigned long long b2 = pk2(bb[j], bb[j]);
                fma2(acc[0][j], am[0], b2);
                fma2(acc[1][j], am[1], b2);
                fma2(acc[2][j], am[2], b2);
                fma2(acc[3][j], am[3], b2);
            }
        }
    }

    float bias[8];
#pragma unroll
    for (int j = 0; j < 8; j++) bias[j] = bih[n0 + tn + j] + bhh[n0 + tn + j];

#pragma unroll
    for (int i = 0; i < 4; i++) {
        float r0v[8], r1v[8];
#pragma unroll
        for (int j = 0; j < 8; j++) {
            float2 p = up2(acc[i][j]);
            r0v[j] = p.x + bias[j];
            r1v[j] = p.y + bias[j];
        }
        size_t row0 = (size_t)(m0 + tm + 2 * i) * GDIM + n0 + tn;
        size_t row1 = row0 + GDIM;
        *(float4*)&g_xgates[row0]     = make_float4(r0v[0], r0v[1], r0v[2], r0v[3]);
        *(float4*)&g_xgates[row0 + 4] = make_float4(r0v[4], r0v[5], r0v[6], r0v[7]);
        *(float4*)&g_xgates[row1]     = make_float4(r1v[0], r1v[1], r1v[2], r1v[3]);
        *(float4*)&g_xgates[row1 + 4] = make_float4(r1v[4], r1v[5], r1v[6], r1v[7]);
    }
}

// ---------------- persistent LSTM recurrence ----------------------------------
// BYTE-EXACT R5 structure (best passing: 34.4 ms) with ONE isolated change:
// 32 counter shards instead of 8. L2-atomic law: arrival queue per line drops
// 16*32*0.854=437 -> 4*32*0.854=109 cyc; the LAST arrival (which gates the
// barrier) no longer eats a 437-cyc RMW queue. Poll-side cost is unchanged
// (per-line poll rate = NBLK / poll-period, independent of shard count).
// Poll: warp 0, lane l watches shard l (ballot loop, R12-proven pattern);
// one __syncthreads broadcasts acquired visibility. All else identical to R5:
// smem h staging, warp-per-element W_hh in registers, lane0 serial epilogue,
// 4 barriers/step, one red.release per CTA per step.
__global__ __launch_bounds__(RTHREADS, 1) void lstm_kernel(const float* __restrict__ Whh) {
    __shared__ __align__(16) float sh_h[HDIM];

    const int tid = threadIdx.x;
    const int w = tid >> 5;             // warp 0..7
    const int lane = tid & 31;
    const int b = blockIdx.x;           // 0..127
    const int e = b * 8 + w;            // owned h element
    const int shard = b >> 2;           // 4 CTAs per shard

    unsigned long long w01[32], w23[32];
#pragma unroll
    for (int c0 = 0; c0 < 32; c0++) {
        int col = lane + 32 * c0;
        w01[c0] = pk2(Whh[(size_t)(0 * HDIM + e) * HDIM + col],
                      Whh[(size_t)(1 * HDIM + e) * HDIM + col]);
        w23[c0] = pk2(Whh[(size_t)(2 * HDIM + e) * HDIM + col],
                      Whh[(size_t)(3 * HDIM + e) * HDIM + col]);
    }

    float c_state = 0.0f;               // lane 0's value is authoritative

    for (int t = 0; t < T_STEPS; t++) {
        // Prefetch this step's 4 xg values (independent of h; hides behind wait)
        float xg0, xg1, xg2, xg3;
        if (lane == 0) {
            const float* xr = &g_xgates[(size_t)t * GDIM + e];
            xg0 = __ldcg(xr);
            xg1 = __ldcg(xr + HDIM);
            xg2 = __ldcg(xr + 2 * HDIM);
            xg3 = __ldcg(xr + 3 * HDIM);
        }

        if (t > 0) {
            if (w == 0) {               // warp 0: lane l polls shard l
                const unsigned target = (unsigned)t * CTAS_PER_SHARD;
                for (;;) {
                    unsigned v = ld_acq(&g_ctr[lane * 32]);
                    if (__all_sync(0xffffffffu, v >= target)) break;
                }
            }
            __syncthreads();            // broadcast acquired visibility CTA-wide
            const float4* hb = (const float4*)g_h[t & 1];
            ((float4*)sh_h)[tid] = __ldcg(&hb[tid]);
        } else {
            ((float4*)sh_h)[tid] = make_float4(0.f, 0.f, 0.f, 0.f);
        }
        __syncthreads();

        unsigned long long acc01 = 0ULL, acc23 = 0ULL;
#pragma unroll
        for (int c0 = 0; c0 < 32; c0++) {
            float hv = sh_h[lane + 32 * c0];        // bank = lane: conflict-free
            unsigned long long hh = pk2(hv, hv);
            fma2(acc01, w01[c0], hh);
            fma2(acc23, w23[c0], hh);
        }
        __syncthreads();   // sh_h consumed; safe to refill next iteration

        float2 s01 = up2(acc01), s23 = up2(acc23);
#pragma unroll
        for (int off = 16; off; off >>= 1) {
            s01.x += __shfl_xor_sync(0xffffffffu, s01.x, off);
            s01.y += __shfl_xor_sync(0xffffffffu, s01.y, off);
            s23.x += __shfl_xor_sync(0xffffffffu, s23.x, off);
            s23.y += __shfl_xor_sync(0xffffffffu, s23.y, off);
        }

        if (lane == 0) {
            float i_ = fast_sigmoid(s01.x + xg0);
            float f_ = fast_sigmoid(s01.y + xg1);
            float g_ = fast_tanh(s23.x + xg2);
            float o_ = fast_sigmoid(s23.y + xg3);
            c_state = f_ * c_state + i_ * g_;
            float hn = o_ * fast_tanh(c_state);
            __stcg(&g_h[(t + 1) & 1][e], hn);
        }
        __syncthreads();   // all 8 h-stores of this CTA issued before arrival

        if (tid == 0) red_rel(&g_ctr[shard * 32]);  // one arrival per CTA
    }
}

// ---------------- final: out = W_lin @ h_last + b_lin -------------------------
__global__ void final_kernel(const float* __restrict__ Wl,
                             const float* __restrict__ bl,
                             float* __restrict__ out) {
    __shared__ float partial[32];
    const int tid = threadIdx.x;     // 1024 threads
    float v = Wl[tid] * g_h[0][tid]; // h(T) lives in buffer (T_STEPS & 1) == 0
#pragma unroll
    for (int off = 16; off; off >>= 1) v += __shfl_xor_sync(0xffffffffu, v, off);
    if ((tid & 31) == 0) partial[tid >> 5] = v;
    __syncthreads();
    if (tid < 32) {
        float s = partial[tid];
#pragma unroll
        for (int off = 16; off; off >>= 1) s += __shfl_xor_sync(0xffffffffu, s, off);
        if (tid == 0) out[0] = s + bl[0];
    }
}

// ---------------- launch -------------------------------------------------------
extern "C" void kernel_launch(void* const* d_in, const int* in_sizes, int n_in,
                              void* d_out, int out_size) {
    const float* input = (const float*)d_in[0];   // [T, I]
    const float* W_ih  = (const float*)d_in[1];   // [4H, I]
    const float* W_hh  = (const float*)d_in[2];   // [4H, H]
    const float* b_ih  = (const float*)d_in[3];   // [4H]
    const float* b_hh  = (const float*)d_in[4];   // [4H]
    const float* W_lin = (const float*)d_in[5];   // [1, H]
    const float* b_lin = (const float*)d_in[6];   // [1]
    float* out = (float*)d_out;

    init_kernel<<<4, 256>>>();

    dim3 ggrid(T_STEPS / 128, GDIM / 128);        // (128, 32)
    gemm_kernel<<<ggrid, 256>>>(input, W_ih, b_ih, b_hh);

    lstm_kernel<<<NBLK, RTHREADS>>>(W_hh);

    final_kernel<<<1, 1024>>>(W_lin, b_lin, out);
}

// round 15
// speedup vs baseline: 1.5255x; 1.0151x over previous
#include <cuda_runtime.h>
#include <math.h>

#define T_STEPS 16384
#define IDIM 1024
#define HDIM 1024
#define GDIM 4096
#define NBLK 128
#define RTHREADS 256
#define NGRP 8                          // barrier counter shards (R5-proven)
#define CTAS_PER_GRP (NBLK / NGRP)      // 16

// ---------------- device globals (scratch; no allocations allowed) ------------
__device__ float g_xgates[(size_t)T_STEPS * GDIM];   // 256 MB input gates
__device__ __align__(16) float g_h[2][HDIM];         // double-buffered hidden state
__device__ unsigned g_ctr[NGRP * 32];                // 8 counters, 128B apart

// ---------------- helpers -----------------------------------------------------
static __device__ __forceinline__ unsigned long long pk2(float lo, float hi) {
    unsigned long long r;
    asm("mov.b64 %0, {%1, %2};" : "=l"(r) : "f"(lo), "f"(hi));
    return r;
}
static __device__ __forceinline__ void fma2(unsigned long long& d,
                                            unsigned long long a,
                                            unsigned long long b) {
    asm("fma.rn.f32x2 %0, %1, %2, %0;" : "+l"(d) : "l"(a), "l"(b));
}
static __device__ __forceinline__ float2 up2(unsigned long long v) {
    float2 f;
    asm("mov.b64 {%0, %1}, %2;" : "=f"(f.x), "=f"(f.y) : "l"(v));
    return f;
}
static __device__ __forceinline__ float fast_sigmoid(float x) {
    return __fdividef(1.0f, 1.0f + __expf(-x));
}
static __device__ __forceinline__ float fast_tanh(float x) {
    return 1.0f - __fdividef(2.0f, __expf(2.0f * x) + 1.0f);
}
static __device__ __forceinline__ unsigned ld_acq(const unsigned* p) {
    unsigned v;
    asm volatile("ld.acquire.gpu.u32 %0, [%1];" : "=r"(v) : "l"(p) : "memory");
    return v;
}
static __device__ __forceinline__ void red_rel(unsigned* p) {
    asm volatile("red.release.gpu.add.u32 [%0], %1;" :: "l"(p), "r"(1u) : "memory");
}
// 3xTF32 split helpers.
static __device__ __forceinline__ void tf32_split(float v, float& hi, float& lo) {
    unsigned h;
    asm("cvt.rna.tf32.f32 %0, %1;" : "=r"(h) : "f"(v));
    hi = __uint_as_float(h);
    float rem = v - hi;
    unsigned l;
    asm("cvt.rna.tf32.f32 %0, %1;" : "=r"(l) : "f"(rem));
    lo = __uint_as_float(l);
}
static __device__ __forceinline__ void mma_tf32(float* c, const unsigned* a,
                                                const unsigned* bfr) {
    asm volatile(
        "mma.sync.aligned.m16n8k8.row.col.f32.tf32.tf32.f32 "
        "{%0,%1,%2,%3}, {%4,%5,%6,%7}, {%8,%9}, {%0,%1,%2,%3};"
        : "+f"(c[0]), "+f"(c[1]), "+f"(c[2]), "+f"(c[3])
        : "r"(a[0]), "r"(a[1]), "r"(a[2]), "r"(a[3]), "r"(bfr[0]), "r"(bfr[1]));
}

// ---------------- init: reset counters each launch (graph replays!) -----------
__global__ void init_kernel() {
    int i = threadIdx.x;
    if (i < NGRP * 32) g_ctr[i] = 0u;
}

// ---------------- GEMM (3xTF32 tensor cores): xg = A @ W^T + (bih + bhh) ------
// CTA tile 128x128, K-tile 8, 8 warps, warp tile 32x64 = 2 m-atoms x 8 n-atoms
// of m16n8k8. hi/lo tf32 split at smem staging. C = A_hi*B_hi + A_hi*B_lo +
// A_lo*B_hi (error ~1e-7, fp32-class).
__global__ __launch_bounds__(256) void gemm_tf32_kernel(
    const float* __restrict__ A, const float* __restrict__ W,
    const float* __restrict__ bih, const float* __restrict__ bhh) {
    __shared__ float As_hi[8][132], As_lo[8][132];
    __shared__ float Bs_hi[8][132], Bs_lo[8][132];
    __shared__ float s_bias[128];

    const int tid = threadIdx.x;
    const int m0 = blockIdx.x * 128;
    const int n0 = blockIdx.y * 128;
    const int lrow = tid >> 1;          // 0..127
    const int kq = (tid & 1) * 4;       // 0 or 4
    const int warp = tid >> 5;
    const int lane = tid & 31;
    const int wm = (warp >> 1) * 32;    // warp m-offset (4 rows of warps)
    const int wn = (warp & 1) * 64;     // warp n-offset (2 cols of warps)
    const int kk = lane & 3;            // frag k index
    const int mr = lane >> 2;           // frag row/col index (0..7)

    if (tid < 128) s_bias[tid] = bih[n0 + tid] + bhh[n0 + tid];

    float c[2][8][4];
#pragma unroll
    for (int im = 0; im < 2; im++)
#pragma unroll
        for (int in = 0; in < 8; in++)
#pragma unroll
            for (int i = 0; i < 4; i++) c[im][in][i] = 0.0f;

    const float* aptr = A + (size_t)(m0 + lrow) * IDIM + kq;
    const float* wptr = W + (size_t)(n0 + lrow) * IDIM + kq;
    float4 av = *(const float4*)aptr;
    float4 bv = *(const float4*)wptr;

    for (int k0 = 0; k0 < IDIM; k0 += 8) {
        __syncthreads();
        {   // split & store transposed: As[k][m], Bs[k][n]
            float h, l;
            tf32_split(av.x, h, l); As_hi[kq + 0][lrow] = h; As_lo[kq + 0][lrow] = l;
            tf32_split(av.y, h, l); As_hi[kq + 1][lrow] = h; As_lo[kq + 1][lrow] = l;
            tf32_split(av.z, h, l); As_hi[kq + 2][lrow] = h; As_lo[kq + 2][lrow] = l;
            tf32_split(av.w, h, l); As_hi[kq + 3][lrow] = h; As_lo[kq + 3][lrow] = l;
            tf32_split(bv.x, h, l); Bs_hi[kq + 0][lrow] = h; Bs_lo[kq + 0][lrow] = l;
            tf32_split(bv.y, h, l); Bs_hi[kq + 1][lrow] = h; Bs_lo[kq + 1][lrow] = l;
            tf32_split(bv.z, h, l); Bs_hi[kq + 2][lrow] = h; Bs_lo[kq + 2][lrow] = l;
            tf32_split(bv.w, h, l); Bs_hi[kq + 3][lrow] = h; Bs_lo[kq + 3][lrow] = l;
        }
        __syncthreads();
        if (k0 + 8 < IDIM) {
            av = *(const float4*)(aptr + k0 + 8);
            bv = *(const float4*)(wptr + k0 + 8);
        }

        // Fragments. A atom im: rows wm+im*16+{mr, mr+8}, cols {kk, kk+4}.
        unsigned Ah[2][4], Al[2][4], Bh[8][2], Bl[8][2];
#pragma unroll
        for (int im = 0; im < 2; im++) {
            int mb = wm + im * 16 + mr;
            Ah[im][0] = __float_as_uint(As_hi[kk][mb]);
            Ah[im][1] = __float_as_uint(As_hi[kk][mb + 8]);
            Ah[im][2] = __float_as_uint(As_hi[kk + 4][mb]);
            Ah[im][3] = __float_as_uint(As_hi[kk + 4][mb + 8]);
            Al[im][0] = __float_as_uint(As_lo[kk][mb]);
            Al[im][1] = __float_as_uint(As_lo[kk][mb + 8]);
            Al[im][2] = __float_as_uint(As_lo[kk + 4][mb]);
            Al[im][3] = __float_as_uint(As_lo[kk + 4][mb + 8]);
        }
#pragma unroll
        for (int in = 0; in < 8; in++) {
            int nb = wn + in * 8 + mr;
            Bh[in][0] = __float_as_uint(Bs_hi[kk][nb]);
            Bh[in][1] = __float_as_uint(Bs_hi[kk + 4][nb]);
            Bl[in][0] = __float_as_uint(Bs_lo[kk][nb]);
            Bl[in][1] = __float_as_uint(Bs_lo[kk + 4][nb]);
        }

#pragma unroll
        for (int im = 0; im < 2; im++)
#pragma unroll
            for (int in = 0; in < 8; in++) {
                mma_tf32(c[im][in], Ah[im], Bh[in]);   // hi*hi
                mma_tf32(c[im][in], Ah[im], Bl[in]);   // hi*lo
                mma_tf32(c[im][in], Al[im], Bh[in]);   // lo*hi
            }
    }

    // Epilogue: c[i] at (m = mr + 8*(i>>1), n = 2*(lane&3) + (i&1)); paired
    // {c0,c1}/{c2,c3} are n-contiguous -> STG.64, fully-used sectors.
#pragma unroll
    for (int im = 0; im < 2; im++) {
#pragma unroll
        for (int in = 0; in < 8; in++) {
            int nloc = wn + in * 8 + 2 * (lane & 3);
            int m_lo = m0 + wm + im * 16 + mr;
            float b0 = s_bias[nloc], b1 = s_bias[nloc + 1];
            float2 v0 = make_float2(c[im][in][0] + b0, c[im][in][1] + b1);
            float2 v1 = make_float2(c[im][in][2] + b0, c[im][in][3] + b1);
            *(float2*)&g_xgates[(size_t)m_lo * GDIM + n0 + nloc] = v0;
            *(float2*)&g_xgates[(size_t)(m_lo + 8) * GDIM + n0 + nloc] = v1;
        }
    }
}

// ---------------- persistent LSTM recurrence (BYTE-EXACT R5 — best: 34.4ms) ---
__global__ __launch_bounds__(RTHREADS, 1) void lstm_kernel(const float* __restrict__ Whh) {
    __shared__ __align__(16) float sh_h[HDIM];

    const int tid = threadIdx.x;
    const int w = tid >> 5;             // warp 0..7
    const int lane = tid & 31;
    const int b = blockIdx.x;           // 0..127
    const int e = b * 8 + w;            // owned h element
    const int grp = b >> 4;             // counter shard

    unsigned long long w01[32], w23[32];
#pragma unroll
    for (int c0 = 0; c0 < 32; c0++) {
        int col = lane + 32 * c0;
        w01[c0] = pk2(Whh[(size_t)(0 * HDIM + e) * HDIM + col],
                      Whh[(size_t)(1 * HDIM + e) * HDIM + col]);
        w23[c0] = pk2(Whh[(size_t)(2 * HDIM + e) * HDIM + col],
                      Whh[(size_t)(3 * HDIM + e) * HDIM + col]);
    }

    float c_state = 0.0f;               // lane 0's value is authoritative

    for (int t = 0; t < T_STEPS; t++) {
        float xg0, xg1, xg2, xg3;
        if (lane == 0) {
            const float* xr = &g_xgates[(size_t)t * GDIM + e];
            xg0 = __ldcg(xr);
            xg1 = __ldcg(xr + HDIM);
            xg2 = __ldcg(xr + 2 * HDIM);
            xg3 = __ldcg(xr + 3 * HDIM);
        }

        if (t > 0) {
            if (tid < NGRP) {
                const unsigned target = (unsigned)t * CTAS_PER_GRP;
                unsigned v;
                do {
                    v = ld_acq(&g_ctr[tid * 32]);
                } while (v < target);
            }
            __syncthreads();            // broadcast acquired visibility CTA-wide
            const float4* hb = (const float4*)g_h[t & 1];
            ((float4*)sh_h)[tid] = __ldcg(&hb[tid]);
        } else {
            ((float4*)sh_h)[tid] = make_float4(0.f, 0.f, 0.f, 0.f);
        }
        __syncthreads();

        unsigned long long acc01 = 0ULL, acc23 = 0ULL;
#pragma unroll
        for (int c0 = 0; c0 < 32; c0++) {
            float hv = sh_h[lane + 32 * c0];        // bank = lane: conflict-free
            unsigned long long hh = pk2(hv, hv);
            fma2(acc01, w01[c0], hh);
            fma2(acc23, w23[c0], hh);
        }
        __syncthreads();   // sh_h consumed; safe to refill next iteration

        float2 s01 = up2(acc01), s23 = up2(acc23);
#pragma unroll
        for (int off = 16; off; off >>= 1) {
            s01.x += __shfl_xor_sync(0xffffffffu, s01.x, off);
            s01.y += __shfl_xor_sync(0xffffffffu, s01.y, off);
            s23.x += __shfl_xor_sync(0xffffffffu, s23.x, off);
            s23.y += __shfl_xor_sync(0xffffffffu, s23.y, off);
        }

        if (lane == 0) {
            float i_ = fast_sigmoid(s01.x + xg0);
            float f_ = fast_sigmoid(s01.y + xg1);
            float g_ = fast_tanh(s23.x + xg2);
            float o_ = fast_sigmoid(s23.y + xg3);
            c_state = f_ * c_state + i_ * g_;
            float hn = o_ * fast_tanh(c_state);
            __stcg(&g_h[(t + 1) & 1][e], hn);
        }
        __syncthreads();   // all 8 h-stores of this CTA issued before arrival

        if (tid == 0) {
            red_rel(&g_ctr[grp * 32]);
        }
    }
}

// ---------------- final: out = W_lin @ h_last + b_lin -------------------------
__global__ void final_kernel(const float* __restrict__ Wl,
                             const float* __restrict__ bl,
                             float* __restrict__ out) {
    __shared__ float partial[32];
    const int tid = threadIdx.x;     // 1024 threads
    float v = Wl[tid] * g_h[0][tid]; // h(T) lives in buffer (T_STEPS & 1) == 0
#pragma unroll
    for (int off = 16; off; off >>= 1) v += __shfl_xor_sync(0xffffffffu, v, off);
    if ((tid & 31) == 0) partial[tid >> 5] = v;
    __syncthreads();
    if (tid < 32) {
        float s = partial[tid];
#pragma unroll
        for (int off = 16; off; off >>= 1) s += __shfl_xor_sync(0xffffffffu, s, off);
        if (tid == 0) out[0] = s + bl[0];
    }
}

// ---------------- launch -------------------------------------------------------
extern "C" void kernel_launch(void* const* d_in, const int* in_sizes, int n_in,
                              void* d_out, int out_size) {
    const float* input = (const float*)d_in[0];   // [T, I]
    const float* W_ih  = (const float*)d_in[1];   // [4H, I]
    const float* W_hh  = (const float*)d_in[2];   // [4H, H]
    const float* b_ih  = (const float*)d_in[3];   // [4H]
    const float* b_hh  = (const float*)d_in[4];   // [4H]
    const float* W_lin = (const float*)d_in[5];   // [1, H]
    const float* b_lin = (const float*)d_in[6];   // [1]
    float* out = (float*)d_out;

    init_kernel<<<1, 256>>>();

    dim3 ggrid(T_STEPS / 128, GDIM / 128);        // (128, 32)
    gemm_tf32_kernel<<<ggrid, 256>>>(input, W_ih, b_ih, b_hh);

    lstm_kernel<<<NBLK, RTHREADS>>>(W_hh);

    final_kernel<<<1, 1024>>>(W_lin, b_lin, out);
}